// round 9
// baseline (speedup 1.0000x reference)
#include <cuda_runtime.h>
#include <cstdint>

#define NDIM 8192
#define THREADS 1024
#define NBLOCKS 148                 // persistent: one CTA per SM
#define DEPTH 4                     // ring slots (rows); 3 groups in flight
#define ROWB 32768u                 // bytes per row (8192 fp32)
#define RING_BYTES (DEPTH * 32768)  // 128 KB ring
#define SMEM_TOTAL RING_BYTES

// Scratch for deterministic final reduction (no cudaMalloc allowed).
__device__ float g_partA[NBLOCKS];
__device__ float g_partB[NBLOCKS];
__device__ int   g_count = 0;

// ---- packed f32x2 helpers (sm_103a) ----
__device__ __forceinline__ void fma2(unsigned long long& d,
                                     unsigned long long a,
                                     unsigned long long b) {
    asm("fma.rn.f32x2 %0, %1, %2, %0;" : "+l"(d) : "l"(a), "l"(b));
}
__device__ __forceinline__ void add2(unsigned long long& d,
                                     unsigned long long a) {
    asm("add.rn.f32x2 %0, %0, %1;" : "+l"(d) : "l"(a));
}
__device__ __forceinline__ float lo2(unsigned long long p) {
    unsigned int l, h;
    asm("mov.b64 {%0, %1}, %2;" : "=r"(l), "=r"(h) : "l"(p));
    return __uint_as_float(l);
}
__device__ __forceinline__ float hi2(unsigned long long p) {
    unsigned int l, h;
    asm("mov.b64 {%0, %1}, %2;" : "=r"(l), "=r"(h) : "l"(p));
    return __uint_as_float(h);
}

// ---- per-thread cp.async helpers ----
__device__ __forceinline__ uint32_t smem_u32(const void* p) {
    uint32_t a;
    asm("{ .reg .u64 t; cvta.to.shared.u64 t, %1; cvt.u32.u64 %0, t; }"
        : "=r"(a) : "l"(p));
    return a;
}
__device__ __forceinline__ void cp16(uint32_t dst, const void* src) {
    asm volatile("cp.async.cg.shared.global [%0], [%1], 16;"
                 :: "r"(dst), "l"(src) : "memory");
}
__device__ __forceinline__ void cp_commit() {
    asm volatile("cp.async.commit_group;" ::: "memory");
}
__device__ __forceinline__ void cp_wait2() {
    asm volatile("cp.async.wait_group 2;" ::: "memory");
}

extern __shared__ char dynsmem[];

__global__ __launch_bounds__(THREADS, 1)
void ising_fused(const float* __restrict__ M, const float* __restrict__ s,
                 float* __restrict__ out) {
    __shared__ float sA[THREADS / 32];
    __shared__ float sB[THREADS / 32];
    __shared__ int s_isLast;

    const int tid = threadIdx.x;
    const int lane = tid & 31;
    const int wid = tid >> 5;
    const int bid = blockIdx.x;

    // Contiguous row partition: 8192 rows over 148 CTAs (55 or 56 each).
    const int rowBeg = (int)(((long long)bid * NDIM) / NBLOCKS);
    const int rowEnd = (int)(((long long)(bid + 1) * NDIM) / NBLOCKS);
    const int n = rowEnd - rowBeg;

    // This thread's fixed vec columns (it copies and consumes ONLY these).
    const int j4a = tid;             // [0, 1024)
    const int j4b = tid + 1024;      // [1024, 2048)
    const uint32_t offA = (uint32_t)j4a * 16u;
    const uint32_t offB = (uint32_t)j4b * 16u;
    const uint32_t ring = smem_u32(dynsmem);

    // s slice lives in registers: loaded once, coalesced.
    const ulonglong2* s64g = reinterpret_cast<const ulonglong2*>(s);
    const ulonglong2 sa = __ldg(s64g + j4a);
    const ulonglong2 sb = __ldg(s64g + j4b);

    // Prologue: prime 3 row-groups (rows rowBeg .. rowBeg+2).
    #pragma unroll
    for (int p = 0; p < DEPTH - 1; ++p) {
        const float* rowp = M + (size_t)(rowBeg + p) * NDIM;   // n >= 55 always
        const uint32_t base = ring + (uint32_t)p * ROWB;
        cp16(base + offA, rowp + (size_t)j4a * 4);
        cp16(base + offB, rowp + (size_t)j4b * 4);
        cp_commit();
    }

    unsigned long long a01 = 0ull, a23 = 0ull;   // packed plain sum
    float amAcc = 0.0f;                          // mixed-vec remainder
    float bAcc  = 0.0f;                          // s_i-weighted upper-dot + diag

    #pragma unroll 1
    for (int k = 0; k < n; ++k) {
        const int row = rowBeg + k;
        const int vs = row >> 2;
        const uint32_t slotBase = (uint32_t)(k & (DEPTH - 1)) * ROWB;

        cp_wait2();    // per-thread: group for row k complete, data visible

        const ulonglong2* m64 =
            reinterpret_cast<const ulonglong2*>(dynsmem + slotBase);
        const ulonglong2 v1 = m64[j4a];     // LDS.128 (own bytes)
        const ulonglong2 v2 = m64[j4b];     // LDS.128
        const float srow = __ldg(s + row);  // uniform, L1-hot

        unsigned long long d01 = 0ull, d23 = 0ull;
        float dm = 0.0f;

        // --- vec 1 (j4a) ---
        if (j4a > vs) {
            add2(a01, v1.x);  add2(a23, v1.y);
            fma2(d01, v1.x, sa.x);  fma2(d23, v1.y, sa.y);
        } else if (j4a < vs) {
            add2(a01, v1.x);  add2(a23, v1.y);
        } else {
            const float vx = lo2(v1.x), vy = hi2(v1.x);
            const float vz = lo2(v1.y), vw = hi2(v1.y);
            const float tx = lo2(sa.x), ty = hi2(sa.x);
            const float tz = lo2(sa.y), tw = hi2(sa.y);
            const int j = j4a * 4;
            amAcc += (vx + vy) + (vz + vw);
            const float w0 = (j + 0 > row) ? tx : ((j + 0 == row) ? 1.0f : 0.0f);
            const float w1 = (j + 1 > row) ? ty : ((j + 1 == row) ? 1.0f : 0.0f);
            const float w2 = (j + 2 > row) ? tz : ((j + 2 == row) ? 1.0f : 0.0f);
            const float w3 = (j + 3 > row) ? tw : ((j + 3 == row) ? 1.0f : 0.0f);
            dm += fmaf(vx, w0, fmaf(vy, w1, fmaf(vz, w2, vw * w3)));
        }

        // --- vec 2 (j4b) ---
        if (j4b > vs) {
            add2(a01, v2.x);  add2(a23, v2.y);
            fma2(d01, v2.x, sb.x);  fma2(d23, v2.y, sb.y);
        } else if (j4b < vs) {
            add2(a01, v2.x);  add2(a23, v2.y);
        } else {
            const float vx = lo2(v2.x), vy = hi2(v2.x);
            const float vz = lo2(v2.y), vw = hi2(v2.y);
            const float tx = lo2(sb.x), ty = hi2(sb.x);
            const float tz = lo2(sb.y), tw = hi2(sb.y);
            const int j = j4b * 4;
            amAcc += (vx + vy) + (vz + vw);
            const float w0 = (j + 0 > row) ? tx : ((j + 0 == row) ? 1.0f : 0.0f);
            const float w1 = (j + 1 > row) ? ty : ((j + 1 == row) ? 1.0f : 0.0f);
            const float w2 = (j + 2 > row) ? tz : ((j + 2 == row) ? 1.0f : 0.0f);
            const float w3 = (j + 3 > row) ? tw : ((j + 3 == row) ? 1.0f : 0.0f);
            dm += fmaf(vx, w0, fmaf(vy, w1, fmaf(vz, w2, vw * w3)));
        }

        const float di = ((lo2(d01) + hi2(d01)) + (lo2(d23) + hi2(d23))) + dm;
        bAcc = fmaf(srow, di, bAcc);

        // Issue row k+3 into slot (k+3)&3 (consumed at k-1: safe reuse),
        // commit ALWAYS to keep per-thread group accounting uniform.
        const int nk = k + DEPTH - 1;
        if (nk < n) {
            const float* rown = M + (size_t)(rowBeg + nk) * NDIM;
            const uint32_t base = ring + (uint32_t)(nk & (DEPTH - 1)) * ROWB;
            cp16(base + offA, rown + (size_t)j4a * 4);
            cp16(base + offB, rown + (size_t)j4b * 4);
        }
        cp_commit();
    }

    float aAcc = ((lo2(a01) + hi2(a01)) + (lo2(a23) + hi2(a23))) + amAcc;

    // Warp shuffle reduction (deterministic).
    #pragma unroll
    for (int off = 16; off > 0; off >>= 1) {
        aAcc += __shfl_xor_sync(0xFFFFFFFFu, aAcc, off);
        bAcc += __shfl_xor_sync(0xFFFFFFFFu, bAcc, off);
    }
    if (lane == 0) { sA[wid] = aAcc; sB[wid] = bAcc; }
    __syncthreads();

    if (tid == 0) {
        float a = 0.f, b = 0.f;
        #pragma unroll
        for (int w = 0; w < THREADS / 32; ++w) { a += sA[w]; b += sB[w]; }
        g_partA[bid] = a;
        g_partB[bid] = b;
        __threadfence();
        const int prev = atomicAdd(&g_count, 1);
        s_isLast = (prev == (int)gridDim.x - 1);
    }
    __syncthreads();

    // Last block: deterministic final reduction in double (reuses ring smem).
    if (s_isLast) {
        double* rA = reinterpret_cast<double*>(dynsmem);
        double* rB = rA + THREADS;
        rA[tid] = (tid < NBLOCKS) ? (double)g_partA[tid] : 0.0;
        rB[tid] = (tid < NBLOCKS) ? (double)g_partB[tid] : 0.0;
        __syncthreads();
        #pragma unroll
        for (int st = THREADS / 2; st > 0; st >>= 1) {
            if (tid < st) { rA[tid] += rA[tid + st]; rB[tid] += rB[tid + st]; }
            __syncthreads();
        }
        if (tid == 0) {
            // out = sum(M)/4 - 0.5 * (sum_{i<j} M_ij s_i s_j + sum_i M_ii s_i)
            out[0] = (float)(rA[0] * 0.25 - 0.5 * rB[0]);
            g_count = 0;   // reset for next graph replay
        }
    }
}

extern "C" void kernel_launch(void* const* d_in, const int* in_sizes, int n_in,
                              void* d_out, int out_size) {
    const float* M = (const float*)d_in[0];   // info_mtx [8192, 8192] fp32
    const float* s = (const float*)d_in[1];   // state [8192] fp32
    float* out = (float*)d_out;

    cudaFuncSetAttribute(ising_fused,
                         cudaFuncAttributeMaxDynamicSharedMemorySize, SMEM_TOTAL);
    ising_fused<<<NBLOCKS, THREADS, SMEM_TOTAL>>>(M, s, out);
}

// round 10
// speedup vs baseline: 1.0052x; 1.0052x over previous
#include <cuda_runtime.h>
#include <cstdint>

#define NDIM 8192
#define THREADS 256
#define NBLOCKS 592                    // 148 SMs * 4 CTAs/SM -> one wave at <=64 regs

// Per-row partials: deterministic regardless of which CTA computes the row.
__device__ float g_rowA[NDIM];
__device__ float g_rowB[NDIM];
__device__ int   g_rowctr = 0;         // dynamic work counter
__device__ int   g_count  = 0;         // completion counter

// Packed f32x2 helpers (sm_103a).
__device__ __forceinline__ void fma2(unsigned long long& d,
                                     unsigned long long a,
                                     unsigned long long b) {
    asm("fma.rn.f32x2 %0, %1, %2, %0;" : "+l"(d) : "l"(a), "l"(b));
}
__device__ __forceinline__ void add2(unsigned long long& d,
                                     unsigned long long a) {
    asm("add.rn.f32x2 %0, %0, %1;" : "+l"(d) : "l"(a));
}
__device__ __forceinline__ float lo2(unsigned long long p) {
    unsigned int l, h;
    asm("mov.b64 {%0, %1}, %2;" : "=r"(l), "=r"(h) : "l"(p));
    return __uint_as_float(l);
}
__device__ __forceinline__ float hi2(unsigned long long p) {
    unsigned int l, h;
    asm("mov.b64 {%0, %1}, %2;" : "=r"(l), "=r"(h) : "l"(p));
    return __uint_as_float(h);
}

__global__ __launch_bounds__(THREADS, 4)
void ising_fused(const float* __restrict__ M, const float* __restrict__ s,
                 float* __restrict__ out) {
    __shared__ float s_sh[NDIM];           // 32 KB staged state vector
    __shared__ float sA[2][THREADS / 32];  // double-buffered per-warp partials
    __shared__ float sB[2][THREADS / 32];
    __shared__ int s_next[2];              // double-buffered next-row index
    __shared__ int s_isLast;

    const int tid  = threadIdx.x;
    const int lane = tid & 31;
    const int wid  = tid >> 5;

    // Stage state vector into shared + grab first row.
    {
        const float4* s4g = reinterpret_cast<const float4*>(s);
        float4* sh4w = reinterpret_cast<float4*>(s_sh);
        #pragma unroll
        for (int k = tid; k < NDIM / 4; k += THREADS) sh4w[k] = s4g[k];
        if (tid == 0) s_next[0] = atomicAdd(&g_rowctr, 1);
    }
    __syncthreads();

    const ulonglong2* s64 = reinterpret_cast<const ulonglong2*>(s_sh);

    int row = s_next[0];
    int q = 0;

    #pragma unroll 1
    while (row < NDIM) {
        const int qn = q ^ 1;
        const ulonglong2* row64 =
            reinterpret_cast<const ulonglong2*>(M + (size_t)row * NDIM);

        // Batch-issue the whole row: 8 independent coalesced LDG.128 (MLP=8),
        // streaming hint (evict-first; M is touched exactly once).
        ulonglong2 v[8];
        #pragma unroll
        for (int k = 0; k < 8; ++k) v[k] = __ldcs(row64 + tid + k * 256);

        // Grab next row while this row's loads are in flight.
        if (tid == 0) s_next[qn] = atomicAdd(&g_rowctr, 1);

        const int vs = row >> 2;          // vec index containing the diagonal
        unsigned long long a01 = 0ull, a23 = 0ull;
        unsigned long long d01 = 0ull, d23 = 0ull;
        float am = 0.0f, dm = 0.0f;

        #pragma unroll
        for (int k = 0; k < 8; ++k) {
            const int j4 = tid + k * 256;
            const ulonglong2 vv = v[k];
            if (j4 > vs) {
                const ulonglong2 tt = s64[j4];       // LDS.128, conflict-free
                add2(a01, vv.x);  add2(a23, vv.y);
                fma2(d01, vv.x, tt.x);  fma2(d23, vv.y, tt.y);
            } else if (j4 < vs) {
                add2(a01, vv.x);  add2(a23, vv.y);
            } else {
                const float vx = lo2(vv.x), vy = hi2(vv.x);
                const float vz = lo2(vv.y), vw = hi2(vv.y);
                const ulonglong2 tt = s64[j4];
                const float tx = lo2(tt.x), ty = hi2(tt.x);
                const float tz = lo2(tt.y), tw = hi2(tt.y);
                const int j = j4 * 4;
                am += (vx + vy) + (vz + vw);
                const float w0 = (j + 0 > row) ? tx : ((j + 0 == row) ? 1.0f : 0.0f);
                const float w1 = (j + 1 > row) ? ty : ((j + 1 == row) ? 1.0f : 0.0f);
                const float w2 = (j + 2 > row) ? tz : ((j + 2 == row) ? 1.0f : 0.0f);
                const float w3 = (j + 3 > row) ? tw : ((j + 3 == row) ? 1.0f : 0.0f);
                dm += fmaf(vx, w0, fmaf(vy, w1, fmaf(vz, w2, vw * w3)));
            }
        }

        // Per-thread row partials.
        float aRow = ((lo2(a01) + hi2(a01)) + (lo2(a23) + hi2(a23))) + am;
        float dRow = ((lo2(d01) + hi2(d01)) + (lo2(d23) + hi2(d23))) + dm;

        // Warp shuffle reduction (fixed order -> deterministic).
        #pragma unroll
        for (int off = 16; off > 0; off >>= 1) {
            aRow += __shfl_xor_sync(0xFFFFFFFFu, aRow, off);
            dRow += __shfl_xor_sync(0xFFFFFFFFu, dRow, off);
        }
        if (lane == 0) { sA[q][wid] = aRow; sB[q][wid] = dRow; }
        __syncthreads();   // publishes sA/sB[q] and s_next[qn]

        if (tid == 0) {
            float a = 0.f, d = 0.f;
            #pragma unroll
            for (int w = 0; w < THREADS / 32; ++w) { a += sA[q][w]; d += sB[q][w]; }
            g_rowA[row] = a;
            g_rowB[row] = s_sh[row] * d;
        }

        row = s_next[qn];
        q = qn;
    }

    // Completion protocol.
    if (tid == 0) {
        __threadfence();
        const int prev = atomicAdd(&g_count, 1);
        s_isLast = (prev == NBLOCKS - 1);
    }
    __syncthreads();

    // Last block: deterministic final reduction in double (fixed row order).
    if (s_isLast) {
        double* rA = reinterpret_cast<double*>(s_sh);
        double* rB = rA + THREADS;
        double a = 0.0, b = 0.0;
        #pragma unroll 4
        for (int k = tid; k < NDIM; k += THREADS) {
            a += (double)g_rowA[k];
            b += (double)g_rowB[k];
        }
        rA[tid] = a;
        rB[tid] = b;
        __syncthreads();
        #pragma unroll
        for (int st = THREADS / 2; st > 0; st >>= 1) {
            if (tid < st) { rA[tid] += rA[tid + st]; rB[tid] += rB[tid + st]; }
            __syncthreads();
        }
        if (tid == 0) {
            // out = sum(M)/4 - 0.5 * (sum_{i<j} M_ij s_i s_j + sum_i M_ii s_i)
            out[0] = (float)(rA[0] * 0.25 - 0.5 * rB[0]);
            g_count = 0;     // reset for next graph replay
            g_rowctr = 0;
        }
    }
}

extern "C" void kernel_launch(void* const* d_in, const int* in_sizes, int n_in,
                              void* d_out, int out_size) {
    const float* M = (const float*)d_in[0];   // info_mtx [8192, 8192] fp32
    const float* s = (const float*)d_in[1];   // state [8192] fp32
    float* out = (float*)d_out;

    ising_fused<<<NBLOCKS, THREADS>>>(M, s, out);
}